// round 12
// baseline (speedup 1.0000x reference)
#include <cuda_runtime.h>
#include <cuda_fp16.h>
#include <math.h>
#include <stdint.h>

static constexpr int B_ = 16;
static constexpr int S_ = 512;
static constexpr int C_ = 7;
static constexpr int D_ = 512;
static constexpr int H_ = 8;
static constexpr int E_ = 64;
static constexpr int DFF_ = 2048;
static constexpr int L_ = 3;
static constexpr int NCLS_ = 10;
static constexpr int PH_ = 64;

static constexpr long DD   = (long)D_*D_;
static constexpr long BSD  = (long)B_*S_*D_;

// ---------------- fp32 scratch ----------------
__device__ float g_x[BSD];
__device__ float g_tmp[BSD];
__device__ float g_final[BSD];
__device__ float g_tau[B_];
__device__ float g_delta[B_*S_];
__device__ float g_bqkv[L_*3*D_];

// ---------------- fragment-ordered fp16 buffers (u32 = half2 pair over k) ----------------
__device__ uint32_t g_xaf[2097152];     // x A-frags   [mtile64][kc16][2048]
__device__ uint32_t g_qaf[2097152];     // q A-frags   [bh][stile4][kc2][2048]
__device__ uint32_t g_kbf[2097152];     // k B-frags   [bh][ntile4][kc2][2048]
__device__ uint32_t g_vbf[2097152];     // v B-frags   [bh][kc16][1024]
__device__ uint32_t g_oaf[2097152];     // o A-frags   [mtile64][kc16][2048]
__device__ uint32_t g_faf[8388608];     // ffn A-frags [mtile64][kc64][2048]
__device__ uint32_t g_wqkvf[1179648];   // [l*3][ntile4][kc16][2048]
__device__ uint32_t g_wof[393216];      // [l][ntile4][kc16][2048]
__device__ uint32_t g_w1f[1572864];     // [l][ntile16][kc16][2048]
__device__ uint32_t g_w2f[1572864];     // [l][ntile4][kc64][2048]

__device__ __forceinline__ float gelu_f(float x) {
    return 0.5f * x * (1.0f + erff(x * 0.70710678118654752440f));
}
__device__ __forceinline__ void mma16816(float* c, const uint32_t* a, const uint32_t* b) {
    asm volatile(
        "mma.sync.aligned.m16n8k16.row.col.f32.f16.f16.f32 "
        "{%0,%1,%2,%3}, {%4,%5,%6,%7}, {%8,%9}, {%0,%1,%2,%3};"
        : "+f"(c[0]), "+f"(c[1]), "+f"(c[2]), "+f"(c[3])
        : "r"(a[0]), "r"(a[1]), "r"(a[2]), "r"(a[3]), "r"(b[0]), "r"(b[1]));
}
__device__ __forceinline__ uint32_t smem_u32(const void* p) {
    uint32_t a;
    asm("{ .reg .u64 t; cvta.to.shared.u64 t, %1; cvt.u32.u64 %0, t; }" : "=r"(a) : "l"(p));
    return a;
}
__device__ __forceinline__ void cp16(uint32_t dst, const void* src) {
    asm volatile("cp.async.ca.shared.global [%0], [%1], 16;" :: "r"(dst), "l"(src));
}
#define CP_COMMIT() asm volatile("cp.async.commit_group;" ::: "memory")
#define CP_WAIT1()  asm volatile("cp.async.wait_group 1;" ::: "memory")
#define CP_WAIT0()  asm volatile("cp.async.wait_group 0;" ::: "memory")

// fragment index helpers
__device__ __forceinline__ int afrag_off(int m128, int k32) {
    int kt = k32 >> 4, msub = m128 >> 4, r16 = m128 & 15, ck = k32 & 15;
    int reg = (r16 >> 3) + ((ck >> 3) << 1);
    int ln  = ((r16 & 7) << 2) + ((ck >> 1) & 3);
    return kt * 1024 + msub * 128 + ln * 4 + reg;
}
__device__ __forceinline__ int bfrag_off128(int n128, int k32) {
    int kt = k32 >> 4, nsub = n128 >> 3, ck = k32 & 15;
    int ln = ((n128 & 7) << 2) + ((ck & 7) >> 1);
    return kt * 1024 + nsub * 64 + ln * 2 + (ck >> 3);
}

// ================= fragment-plane fp16 GEMM, 256x128 tile, cp.async 3-stage =================
// EOUT: 0=f32 row-major, 1=A-frag u32 out, 2=qkv frag out (hh selects q/k/v)
// EPI : 0=+bias, 1=+bias+gelu
// 8 warps: mw=wid&3 (64 rows each), nw=wid>>2 (64 cols each)
template<int EOUT, int EPI>
__global__ void __launch_bounds__(256, 1) fgemm(
    const uint32_t* __restrict__ Af, long Az,
    const uint32_t* __restrict__ Bf, long Bz,
    int K, int hmod,
    const float* __restrict__ bias, int biasMul,
    float* __restrict__ C, int ldc, long dC, long mC,
    uint32_t* __restrict__ Of, int NKCH, int mAddMul, int kAddMul)
{
    constexpr int SST = 6144;                 // u32 per stage: A 4096 + B 2048

    extern __shared__ uint32_t smem[];
    const uint32_t sbase = smem_u32(smem);

    const int tid = threadIdx.x, wid = tid >> 5, lane = tid & 31;
    const int mw = wid & 3, nw = wid >> 2;
    const int bz = blockIdx.z;
    const int bb = bz / hmod, hh = bz - bb * hmod;
    const int nchunk = K >> 5;

    const uint32_t* Ab0 = Af + (long)bz * Az + (long)(2 * blockIdx.x) * nchunk * 2048;
    const uint32_t* Ab1 = Ab0 + (long)nchunk * 2048;
    const uint32_t* Bb  = Bf + (long)bz * Bz + (long)blockIdx.y * nchunk * 2048;
    const int m0 = blockIdx.x * 256;
    const int n0 = blockIdx.y * 128;

    float acc[4][8][4];
    #pragma unroll
    for (int i = 0; i < 4; i++)
        #pragma unroll
        for (int j = 0; j < 8; j++)
            #pragma unroll
            for (int r = 0; r < 4; r++) acc[i][j][r] = 0.f;

    auto issue = [&](int c, int st) {
        uint32_t sa = sbase + st * (SST * 4);
        const uint32_t* A0c = Ab0 + (long)c * 2048;
        const uint32_t* A1c = Ab1 + (long)c * 2048;
        cp16(sa +     tid * 16, A0c + tid * 4);
        cp16(sa + 4096 + tid * 16, A0c + 1024 + tid * 4);
        cp16(sa + 8192 + tid * 16, A1c + tid * 4);
        cp16(sa + 12288 + tid * 16, A1c + 1024 + tid * 4);
        uint32_t sb = sa + 16384;
        const uint32_t* Bc = Bb + (long)c * 2048;
        cp16(sb + tid * 16, Bc + tid * 4);
        cp16(sb + 4096 + tid * 16, Bc + 1024 + tid * 4);
    };

    issue(0, 0); CP_COMMIT();
    if (nchunk > 1) issue(1, 1);
    CP_COMMIT();

    int cur = 0;
    for (int c = 0; c < nchunk; c++) {
        CP_WAIT1();
        __syncthreads();
        int nc = c + 2;
        if (nc < nchunk) {
            int nst = cur + 2; if (nst >= 3) nst -= 3;
            issue(nc, nst);
        }
        CP_COMMIT();

        const uint32_t* bAp = smem + cur * SST + (mw >> 1) * 2048;   // mt2 select
        const uint32_t* bBp = smem + cur * SST + 4096;
        #pragma unroll
        for (int kt = 0; kt < 2; kt++) {
            uint32_t ah[4][4];
            #pragma unroll
            for (int ms = 0; ms < 4; ms++) {
                int msub = (mw & 1) * 4 + ms;
                *(uint4*)ah[ms] = *(const uint4*)&bAp[((kt * 8 + msub) << 7) + lane * 4];
            }
            #pragma unroll
            for (int ns = 0; ns < 8; ns++) {
                int nsub = nw * 8 + ns;
                uint32_t bh[2];
                *(uint2*)bh = *(const uint2*)&bBp[((kt * 16 + nsub) << 6) + lane * 2];
                #pragma unroll
                for (int ms = 0; ms < 4; ms++)
                    mma16816(acc[ms][ns], ah[ms], bh);
            }
        }
        cur++; if (cur == 3) cur = 0;
    }

    // ---- epilogue ----
    #pragma unroll
    for (int ms = 0; ms < 4; ms++) {
        #pragma unroll
        for (int ns = 0; ns < 8; ns++) {
            int mb = m0 + (mw >> 1) * 128 + (mw & 1) * 64 + ms * 16 + (lane >> 2);
            int n  = n0 + nw * 64 + ns * 8 + (lane & 3) * 2;
            float* cr = acc[ms][ns];
            float b0 = 0.f, b1 = 0.f;
            if (bias) { b0 = bias[hh * biasMul + n]; b1 = bias[hh * biasMul + n + 1]; }
            #pragma unroll
            for (int h = 0; h < 2; h++) {
                int m = mb + h * 8;
                float c0 = cr[h * 2 + 0] + b0, c1 = cr[h * 2 + 1] + b1;
                if (EPI == 1) { c0 = gelu_f(c0); c1 = gelu_f(c1); }
                if (EOUT == 0) {
                    float2 o; o.x = c0; o.y = c1;
                    *(float2*)(C + (long)bb * dC + (long)hh * mC + (long)m * ldc + n) = o;
                } else if (EOUT == 1) {
                    __half2 hv = __floats2half2_rn(c0, c1);
                    long mg = (long)bb * mAddMul + m;
                    int  kg = hh * kAddMul + n;
                    Of[((mg >> 7) * (long)NKCH + (kg >> 5)) * 2048 + afrag_off((int)(mg & 127), kg & 31)] = *(uint32_t*)&hv;
                } else {  // EOUT == 2: QKV
                    int b = m >> 9, sl = m & 511;
                    int hh2 = n >> 6, e = n & 63;
                    if (hh == 0) {
                        __half2 hv = __floats2half2_rn(c0, c1);
                        long base = (((long)(b * 8 + hh2) * 4 + (sl >> 7)) * 2 + (e >> 5)) * 2048;
                        g_qaf[base + afrag_off(sl & 127, e & 31)] = *(uint32_t*)&hv;
                    } else if (hh == 1) {
                        __half2 hv = __floats2half2_rn(c0, c1);
                        long base = (((long)(b * 8 + hh2) * 4 + (sl >> 7)) * 2 + (e >> 5)) * 2048;
                        g_kbf[base + bfrag_off128(sl & 127, e & 31)] = *(uint32_t*)&hv;
                    } else {
                        __half* v16 = (__half*)g_vbf;
                        #pragma unroll
                        for (int q = 0; q < 2; q++) {
                            int ee = e + q;
                            float vv = q ? c1 : c0;
                            long u32i = (((long)(b * 8 + hh2) * 16 + (sl >> 5)) * 1024)
                                      + ((sl >> 4) & 1) * 512 + (ee >> 3) * 64
                                      + (((ee & 7) << 2) + ((sl & 7) >> 1)) * 2 + ((sl & 15) >> 3);
                            v16[u32i * 2 + (sl & 1)] = __float2half_rn(vv);
                        }
                    }
                }
            }
        }
    }
}

// ================= fused flash attention =================
// grid (4, 1, 128): x=q-tile, z=bh.  8 warps x 16 Q-rows, full 128-col K tiles per warp.
__global__ void __launch_bounds__(256, 1) flash_kernel(
    const uint32_t* __restrict__ Qf, const uint32_t* __restrict__ Kf,
    const uint32_t* __restrict__ Vf,
    const float* __restrict__ tau, const float* __restrict__ delta,
    uint32_t* __restrict__ Of)
{
    extern __shared__ uint32_t smem[];
    const uint32_t sbase = smem_u32(smem);
    float* sdelta = (float*)(smem + 16384);

    const int tid = threadIdx.x, wid = tid >> 5, lane = tid & 31;
    const int qt = blockIdx.x;
    const int bh = blockIdx.z;
    const int b = bh >> 3, h = bh & 7;

    const float tv = 0.125f * tau[b];
    #pragma unroll
    for (int i = 0; i < 2; i++)
        sdelta[tid + i*256] = 0.125f * delta[b*512 + tid + i*256];

    // Q a-frags: 4 k16 steps (E=64), resident in regs
    uint32_t qf[4][4];
    {
        const uint32_t* Qb = Qf + ((long)bh*4 + qt) * 4096;
        #pragma unroll
        for (int ks = 0; ks < 4; ks++) {
            int kc = ks >> 1, kt = ks & 1;
            *(uint4*)qf[ks] = *(const uint4*)&Qb[kc*2048 + kt*1024 + wid*128 + lane*4];
        }
    }

    const uint32_t* Kb = Kf + (long)bh * 16384;
    const uint32_t* Vb = Vf + (long)bh * 16384;

    auto issue = [&](int t, int st) {
        uint32_t sK = sbase + st * 32768;
        uint32_t sV = sK + 16384;
        #pragma unroll
        for (int j = 0; j < 4; j++) {
            cp16(sK + (tid*4 + j*1024)*4, Kb + (long)t*4096 + tid*4 + j*1024);
            cp16(sV + (tid*4 + j*1024)*4, Vb + (long)t*4096 + tid*4 + j*1024);
        }
    };

    float oacc[8][4];
    #pragma unroll
    for (int ns = 0; ns < 8; ns++)
        #pragma unroll
        for (int r = 0; r < 4; r++) oacc[ns][r] = 0.f;
    float m_r = -1e30f, m_r8 = -1e30f, l_r = 0.f, l_r8 = 0.f;

    issue(0, 0); CP_COMMIT();

    for (int t = 0; t < 4; t++) {
        if (t + 1 < 4) { issue(t + 1, (t + 1) & 1); CP_COMMIT(); CP_WAIT1(); }
        else { CP_WAIT0(); }
        __syncthreads();
        const uint32_t* sK = smem + (t & 1) * 8192;
        const uint32_t* sV = sK + 4096;

        // S = Q K^T  (M=16/warp, N=128, k=64)
        float sacc[16][4];
        #pragma unroll
        for (int ns = 0; ns < 16; ns++)
            #pragma unroll
            for (int r = 0; r < 4; r++) sacc[ns][r] = 0.f;
        #pragma unroll
        for (int ks = 0; ks < 4; ks++) {
            int kc = ks >> 1, kt = ks & 1;
            #pragma unroll
            for (int ns = 0; ns < 16; ns++) {
                uint32_t bf[2];
                *(uint2*)bf = *(const uint2*)&sK[kc*2048 + kt*1024 + ns*64 + lane*2];
                mma16816(sacc[ns], qf[ks], bf);
            }
        }
        // scale + delta
        #pragma unroll
        for (int ns = 0; ns < 16; ns++) {
            int c = t*128 + ns*8 + (lane & 3)*2;
            float d0 = sdelta[c], d1 = sdelta[c + 1];
            sacc[ns][0] = fmaf(sacc[ns][0], tv, d0);
            sacc[ns][1] = fmaf(sacc[ns][1], tv, d1);
            sacc[ns][2] = fmaf(sacc[ns][2], tv, d0);
            sacc[ns][3] = fmaf(sacc[ns][3], tv, d1);
        }
        // tile row max
        float tm_r = -1e30f, tm_r8 = -1e30f;
        #pragma unroll
        for (int ns = 0; ns < 16; ns++) {
            tm_r  = fmaxf(tm_r,  fmaxf(sacc[ns][0], sacc[ns][1]));
            tm_r8 = fmaxf(tm_r8, fmaxf(sacc[ns][2], sacc[ns][3]));
        }
        #pragma unroll
        for (int o = 1; o <= 2; o <<= 1) {
            tm_r  = fmaxf(tm_r,  __shfl_xor_sync(0xffffffffu, tm_r,  o));
            tm_r8 = fmaxf(tm_r8, __shfl_xor_sync(0xffffffffu, tm_r8, o));
        }
        float mn_r = fmaxf(m_r, tm_r), mn_r8 = fmaxf(m_r8, tm_r8);
        float cor_r = __expf(m_r - mn_r), cor_r8 = __expf(m_r8 - mn_r8);
        m_r = mn_r; m_r8 = mn_r8;
        float rs_r = 0.f, rs_r8 = 0.f;
        #pragma unroll
        for (int ns = 0; ns < 16; ns++) {
            sacc[ns][0] = __expf(sacc[ns][0] - m_r);
            sacc[ns][1] = __expf(sacc[ns][1] - m_r);
            sacc[ns][2] = __expf(sacc[ns][2] - m_r8);
            sacc[ns][3] = __expf(sacc[ns][3] - m_r8);
            rs_r  += sacc[ns][0] + sacc[ns][1];
            rs_r8 += sacc[ns][2] + sacc[ns][3];
        }
        #pragma unroll
        for (int o = 1; o <= 2; o <<= 1) {
            rs_r  += __shfl_xor_sync(0xffffffffu, rs_r,  o);
            rs_r8 += __shfl_xor_sync(0xffffffffu, rs_r8, o);
        }
        l_r = l_r * cor_r + rs_r;
        l_r8 = l_r8 * cor_r8 + rs_r8;
        #pragma unroll
        for (int ns = 0; ns < 8; ns++) {
            oacc[ns][0] *= cor_r;  oacc[ns][1] *= cor_r;
            oacc[ns][2] *= cor_r8; oacc[ns][3] *= cor_r8;
        }
        // O += P V
        #pragma unroll
        for (int kk = 0; kk < 8; kk++) {
            uint32_t pa[4];
            __half2 hv;
            hv = __floats2half2_rn(sacc[2*kk][0],   sacc[2*kk][1]);   pa[0] = *(uint32_t*)&hv;
            hv = __floats2half2_rn(sacc[2*kk][2],   sacc[2*kk][3]);   pa[1] = *(uint32_t*)&hv;
            hv = __floats2half2_rn(sacc[2*kk+1][0], sacc[2*kk+1][1]); pa[2] = *(uint32_t*)&hv;
            hv = __floats2half2_rn(sacc[2*kk+1][2], sacc[2*kk+1][3]); pa[3] = *(uint32_t*)&hv;
            int kc2 = kk >> 1, kt2 = kk & 1;
            #pragma unroll
            for (int ns = 0; ns < 8; ns++) {
                uint32_t bf[2];
                *(uint2*)bf = *(const uint2*)&sV[kc2*1024 + kt2*512 + ns*64 + lane*2];
                mma16816(oacc[ns], pa, bf);
            }
        }
        __syncthreads();
    }

    // normalize + write O a-frags
    float inv_r = 1.f / l_r, inv_r8 = 1.f / l_r8;
    int r16 = lane >> 2;
    #pragma unroll
    for (int ns = 0; ns < 8; ns++) {
        int e = ns*8 + (lane & 3)*2;
        __half2 h0 = __floats2half2_rn(oacc[ns][0]*inv_r,  oacc[ns][1]*inv_r);
        __half2 h1 = __floats2half2_rn(oacc[ns][2]*inv_r8, oacc[ns][3]*inv_r8);
        long base = ((long)(b*4 + qt) * 16 + h*2 + (e >> 5)) * 2048;
        Of[base + afrag_off(wid*16 + r16,     e & 31)] = *(uint32_t*)&h0;
        Of[base + afrag_off(wid*16 + r16 + 8, e & 31)] = *(uint32_t*)&h1;
    }
}

// ---------------- weight fragment conversion ----------------
__global__ void cvt_w_qkv(const float* __restrict__ Wq, const float* __restrict__ Wk,
                          const float* __restrict__ Wv, uint32_t* __restrict__ dst)
{
    long i = (long)blockIdx.x * 256 + threadIdx.x;      // pair index
    if (i >= (long)L_ * 3 * 512 * 256) return;
    int kp = (int)(i & 255);
    int n  = (int)((i >> 8) & 511);
    int ls = (int)(i >> 17);
    int l = ls / 3, s = ls - l * 3;
    const float* src = (s == 0 ? Wq : (s == 1 ? Wk : Wv)) + (long)l * DD + (long)n * 512 + kp * 2;
    float2 v = *(const float2*)src;
    __half2 h = __floats2half2_rn(v.x, v.y);
    int k = kp * 2;
    long base = (long)ls * 131072 + ((long)(n >> 7) * 16 + (k >> 5)) * 2048;
    dst[base + bfrag_off128(n & 127, k & 31)] = *(uint32_t*)&h;
}

__global__ void cvt_w(const float* __restrict__ W, uint32_t* __restrict__ dst,
                      int N, int Kd, long perL)
{
    long i = (long)blockIdx.x * 256 + threadIdx.x;
    long Kh = Kd >> 1;
    long tot = (long)L_ * N * Kh;
    if (i >= tot) return;
    int kp = (int)(i % Kh);
    long r = i / Kh;
    int n = (int)(r % N);
    int l = (int)(r / N);
    const float* src = W + ((long)l * N + n) * Kd + kp * 2;
    float2 v = *(const float2*)src;
    __half2 h = __floats2half2_rn(v.x, v.y);
    int k = kp * 2;
    long base = (long)l * perL + ((long)(n >> 7) * (Kd >> 5) + (k >> 5)) * 2048;
    dst[base + bfrag_off128(n & 127, k & 31)] = *(uint32_t*)&h;
}

__global__ void concat_bias(const float* __restrict__ bq, const float* __restrict__ bk,
                            const float* __restrict__ bv, float* __restrict__ d)
{
    int i = blockIdx.x * 256 + threadIdx.x;
    if (i < L_*3*D_) {
        int l = i / (3*D_);
        int rem = i - l*3*D_;
        int sel = rem / D_;
        int off = rem - sel*D_;
        d[i] = (sel == 0 ? bq : (sel == 1 ? bk : bv))[l*D_ + off];
    }
}

// ---------------- tau/delta projectors ----------------
__global__ void proj_kernel(const float* __restrict__ x_enc,
                            const float* __restrict__ tau_conv, const float* __restrict__ tau_w1,
                            const float* __restrict__ tau_b1, const float* __restrict__ tau_w2,
                            const float* __restrict__ del_conv, const float* __restrict__ del_w1,
                            const float* __restrict__ del_b1, const float* __restrict__ del_w2)
{
    int b = blockIdx.x;
    int tid = threadIdx.x;               // 256
    __shared__ float s_mean[C_], s_std[C_], s_yt[C_], s_yd[C_], s_ht[PH_], s_hd[PH_];

    if (tid < C_) {
        float s = 0.f, s2 = 0.f;
        for (int i = 0; i < S_; i++) {
            float v = x_enc[((long)b*S_ + i)*C_ + tid];
            s += v; s2 += v*v;
        }
        float mu = s * (1.f/S_);
        s_mean[tid] = mu;
        s_std[tid] = sqrtf(fmaxf(s2*(1.f/S_) - mu*mu, 0.f) + 1e-5f);
    }
    int w = tid >> 5, lane = tid & 31;
    if (w < C_) {
        int j = w;
        int jm = (j+6)%7, jp = (j+1)%7;
        float at = 0.f, ad = 0.f;
        for (int i = lane; i < S_; i += 32) {
            const float* xr = x_enc + ((long)b*S_ + i)*C_;
            float x0 = xr[jm], x1 = xr[j], x2 = xr[jp];
            const float* wt = tau_conv + i*3;
            const float* wd = del_conv + i*3;
            at += wt[0]*x0 + wt[1]*x1 + wt[2]*x2;
            ad += wd[0]*x0 + wd[1]*x1 + wd[2]*x2;
        }
        #pragma unroll
        for (int o = 16; o; o >>= 1) {
            at += __shfl_xor_sync(0xffffffffu, at, o);
            ad += __shfl_xor_sync(0xffffffffu, ad, o);
        }
        if (lane == 0) { s_yt[j] = at; s_yd[j] = ad; }
    }
    __syncthreads();
    if (tid < PH_) {
        float st = tau_b1[tid], sd = del_b1[tid];
        #pragma unroll
        for (int f = 0; f < 14; f++) {
            float ft = (f < 7) ? s_yt[f] : s_std[f-7];
            float fd = (f < 7) ? s_yd[f] : s_mean[f-7];
            st += tau_w1[tid*14 + f] * ft;
            sd += del_w1[tid*14 + f] * fd;
        }
        s_ht[tid] = fmaxf(st, 0.f);
        s_hd[tid] = fmaxf(sd, 0.f);
    }
    __syncthreads();
    if (tid < 32) {
        float t = s_ht[tid]*tau_w2[tid] + s_ht[tid+32]*tau_w2[tid+32];
        #pragma unroll
        for (int o = 16; o; o >>= 1) t += __shfl_xor_sync(0xffffffffu, t, o);
        if (tid == 0) g_tau[b] = expf(t);
    }
    for (int s = tid; s < S_; s += 256) {
        float acc = 0.f;
        const float* wr = del_w2 + s*PH_;
        #pragma unroll
        for (int p = 0; p < PH_; p++) acc += s_hd[p] * wr[p];
        g_delta[(long)b*S_ + s] = acc;
    }
}

// ---------------- token embedding + PE (fp32 + A-frag out) ----------------
__global__ void embed_kernel(const float* __restrict__ x_enc, const float* __restrict__ tok_w)
{
    int row = blockIdx.x;                // b*S + s
    int b = row >> 9, s = row & 511;
    __shared__ float xs[3][C_];
    int tid = threadIdx.x;               // 128
    if (tid < 21) {
        int r = tid / 7, c = tid % 7;
        int sp = (s - 1 + r + S_) % S_;
        xs[r][c] = x_enc[((long)b*S_ + sp)*C_ + c];
    }
    __syncthreads();
    #pragma unroll
    for (int i = 0; i < 2; i++) {
        int d = 2*tid + i*256;
        float div = expf((float)d * (-9.2103403719761836f / (float)D_));
        float ang = (float)s * div;
        float pe0 = sinf(ang), pe1 = cosf(ang);
        float a0 = pe0, a1 = pe1;
        const float* w0 = tok_w + (long)d*21;
        const float* w1 = w0 + 21;
        #pragma unroll
        for (int r = 0; r < 3; r++)
            #pragma unroll
            for (int c = 0; c < 7; c++) {
                float xv = xs[r][c];
                a0 = fmaf(w0[c*3 + r], xv, a0);
                a1 = fmaf(w1[c*3 + r], xv, a1);
            }
        float2 o; o.x = a0; o.y = a1;
        *(float2*)(g_x + (long)row*D_ + d) = o;
        __half2 hv = __floats2half2_rn(a0, a1);
        g_xaf[((long)(row >> 7) * 16 + (d >> 5)) * 2048 + afrag_off(row & 127, d & 31)] = *(uint32_t*)&hv;
    }
}

// ---------------- residual add + LayerNorm (fp32 + A-frag out) ----------------
__global__ void add_ln_kernel(const float* __restrict__ xr, const float* __restrict__ ar,
                              const float* __restrict__ g, const float* __restrict__ bt,
                              float* __restrict__ out)
{
    long row = blockIdx.x;
    int tid = threadIdx.x;               // 128
    const float* xp = xr + row*D_;
    const float* ap = ar + row*D_;
    float v[4];
    {
        float2 x0 = *(const float2*)(xp + 2*tid);
        float2 a0 = *(const float2*)(ap + 2*tid);
        float2 x1 = *(const float2*)(xp + 2*tid + 256);
        float2 a1 = *(const float2*)(ap + 2*tid + 256);
        v[0] = x0.x + a0.x; v[1] = x0.y + a0.y;
        v[2] = x1.x + a1.x; v[3] = x1.y + a1.y;
    }
    float s = v[0]+v[1]+v[2]+v[3];
    float s2 = v[0]*v[0]+v[1]*v[1]+v[2]*v[2]+v[3]*v[3];
    __shared__ float shs[4], sh2[4];
    #pragma unroll
    for (int o = 16; o; o >>= 1) {
        s  += __shfl_xor_sync(0xffffffffu, s, o);
        s2 += __shfl_xor_sync(0xffffffffu, s2, o);
    }
    int w = tid >> 5, lane = tid & 31;
    if (lane == 0) { shs[w] = s; sh2[w] = s2; }
    __syncthreads();
    s  = shs[0] + shs[1] + shs[2] + shs[3];
    s2 = sh2[0] + sh2[1] + sh2[2] + sh2[3];
    float mean = s * (1.f/D_);
    float var = s2 * (1.f/D_) - mean*mean;
    float r = rsqrtf(var + 1e-5f);
    #pragma unroll
    for (int i = 0; i < 2; i++) {
        int c = 2*tid + i*256;
        float n0 = (v[i*2]   - mean) * r * g[c]   + bt[c];
        float n1 = (v[i*2+1] - mean) * r * g[c+1] + bt[c+1];
        float2 o; o.x = n0; o.y = n1;
        *(float2*)(out + row*D_ + c) = o;
        __half2 hv = __floats2half2_rn(n0, n1);
        g_xaf[((long)(row >> 7) * 16 + (c >> 5)) * 2048 + afrag_off((int)(row & 127), c & 31)] = *(uint32_t*)&hv;
    }
}

// ---------------- final LN + GELU + mask ----------------
__global__ void lnf_kernel(const float* __restrict__ xr,
                           const float* __restrict__ g, const float* __restrict__ bt,
                           const float* __restrict__ mark, float* __restrict__ out)
{
    long row = blockIdx.x;
    int tid = threadIdx.x;               // 128
    const float* xp = xr + row*D_;
    float v[4];
    float s = 0.f, s2 = 0.f;
    #pragma unroll
    for (int i = 0; i < 4; i++) {
        float t = xp[tid + i*128];
        v[i] = t; s += t; s2 += t*t;
    }
    __shared__ float shs[4], sh2[4];
    #pragma unroll
    for (int o = 16; o; o >>= 1) {
        s  += __shfl_xor_sync(0xffffffffu, s, o);
        s2 += __shfl_xor_sync(0xffffffffu, s2, o);
    }
    int w = tid >> 5, lane = tid & 31;
    if (lane == 0) { shs[w] = s; sh2[w] = s2; }
    __syncthreads();
    s  = shs[0] + shs[1] + shs[2] + shs[3];
    s2 = sh2[0] + sh2[1] + sh2[2] + sh2[3];
    float mean = s * (1.f/D_);
    float var = s2 * (1.f/D_) - mean*mean;
    float r = rsqrtf(var + 1e-5f);
    float mk = mark[row];
    #pragma unroll
    for (int i = 0; i < 4; i++) {
        int c = tid + i*128;
        float val = (v[i] - mean) * r * g[c] + bt[c];
        out[row*D_ + c] = gelu_f(val) * mk;
    }
}

// ---------------- final classifier GEMV ----------------
__global__ void final_kernel(const float* __restrict__ gfin, const float* __restrict__ pw,
                             const float* __restrict__ pb, float* __restrict__ out)
{
    int idx = blockIdx.x;
    int b = idx / NCLS_, n = idx - b*NCLS_;
    const float* gp = gfin + (long)b*S_*D_;
    const float* wp = pw + (long)n*S_*D_;
    float s = 0.f;
    for (int k = threadIdx.x*4; k < S_*D_; k += 256*4) {
        float4 a  = *(const float4*)(gp + k);
        float4 w4 = *(const float4*)(wp + k);
        s += a.x*w4.x + a.y*w4.y + a.z*w4.z + a.w*w4.w;
    }
    __shared__ float sh[8];
    #pragma unroll
    for (int o = 16; o; o >>= 1) s += __shfl_xor_sync(0xffffffffu, s, o);
    if ((threadIdx.x & 31) == 0) sh[threadIdx.x >> 5] = s;
    __syncthreads();
    if (threadIdx.x == 0) {
        float t = 0.f;
        #pragma unroll
        for (int i = 0; i < 8; i++) t += sh[i];
        out[idx] = t + pb[n];
    }
}

// ---------------- host ----------------
extern "C" void kernel_launch(void* const* d_in, const int* in_sizes, int n_in,
                              void* d_out, int out_size)
{
    const float* x_enc    = (const float*)d_in[0];
    const float* x_mark   = (const float*)d_in[1];
    const float* tok_w    = (const float*)d_in[2];
    const float* Wq       = (const float*)d_in[3];
    const float* bq       = (const float*)d_in[4];
    const float* Wk       = (const float*)d_in[5];
    const float* bk       = (const float*)d_in[6];
    const float* Wv       = (const float*)d_in[7];
    const float* bv       = (const float*)d_in[8];
    const float* Wo       = (const float*)d_in[9];
    const float* bo       = (const float*)d_in[10];
    const float* W1       = (const float*)d_in[11];
    const float* b1       = (const float*)d_in[12];
    const float* W2       = (const float*)d_in[13];
    const float* b2       = (const float*)d_in[14];
    const float* ln1g     = (const float*)d_in[15];
    const float* ln1b     = (const float*)d_in[16];
    const float* ln2g     = (const float*)d_in[17];
    const float* ln2b     = (const float*)d_in[18];
    const float* lnfg     = (const float*)d_in[19];
    const float* lnfb     = (const float*)d_in[20];
    const float* proj_w   = (const float*)d_in[21];
    const float* proj_b   = (const float*)d_in[22];
    const float* tau_conv = (const float*)d_in[23];
    const float* tau_w1   = (const float*)d_in[24];
    const float* tau_b1   = (const float*)d_in[25];
    const float* tau_w2   = (const float*)d_in[26];
    const float* del_conv = (const float*)d_in[27];
    const float* del_w1   = (const float*)d_in[28];
    const float* del_b1   = (const float*)d_in[29];
    const float* del_w2   = (const float*)d_in[30];

    float *px, *ptmp, *ptau, *pdelta, *pfin, *pbqkv;
    uint32_t *pxaf, *pqaf, *pkbf, *pvbf, *poaf, *pfaf, *pwqkvf, *pwof, *pw1f, *pw2f;
    cudaGetSymbolAddress((void**)&px,    g_x);
    cudaGetSymbolAddress((void**)&ptmp,  g_tmp);
    cudaGetSymbolAddress((void**)&ptau,  g_tau);
    cudaGetSymbolAddress((void**)&pdelta,g_delta);
    cudaGetSymbolAddress((void**)&pfin,  g_final);
    cudaGetSymbolAddress((void**)&pbqkv, g_bqkv);
    cudaGetSymbolAddress((void**)&pxaf,  g_xaf);
    cudaGetSymbolAddress((void**)&pqaf,  g_qaf);
    cudaGetSymbolAddress((void**)&pkbf,  g_kbf);
    cudaGetSymbolAddress((void**)&pvbf,  g_vbf);
    cudaGetSymbolAddress((void**)&poaf,  g_oaf);
    cudaGetSymbolAddress((void**)&pfaf,  g_faf);
    cudaGetSymbolAddress((void**)&pwqkvf,g_wqkvf);
    cudaGetSymbolAddress((void**)&pwof,  g_wof);
    cudaGetSymbolAddress((void**)&pw1f,  g_w1f);
    cudaGetSymbolAddress((void**)&pw2f,  g_w2f);

    const int SMGM = 3 * 6144 * 4;             // 73728
    const int SMFL = 2 * 32768 + 2048;         // 67584
    cudaFuncSetAttribute(fgemm<2,0>, cudaFuncAttributeMaxDynamicSharedMemorySize, SMGM);
    cudaFuncSetAttribute(fgemm<0,0>, cudaFuncAttributeMaxDynamicSharedMemorySize, SMGM);
    cudaFuncSetAttribute(fgemm<1,1>, cudaFuncAttributeMaxDynamicSharedMemorySize, SMGM);
    cudaFuncSetAttribute(flash_kernel, cudaFuncAttributeMaxDynamicSharedMemorySize, SMFL);

    // weight fragment conversions
    cvt_w_qkv<<<4608, 256>>>(Wq, Wk, Wv, pwqkvf);
    cvt_w<<<1536, 256>>>(Wo, pwof, 512, 512, 131072);
    cvt_w<<<6144, 256>>>(W1, pw1f, 2048, 512, 524288);
    cvt_w<<<6144, 256>>>(W2, pw2f, 512, 2048, 524288);
    concat_bias<<<(L_*3*D_ + 255)/256, 256>>>(bq, bk, bv, pbqkv);

    proj_kernel<<<B_, 256>>>(x_enc, tau_conv, tau_w1, tau_b1, tau_w2,
                             del_conv, del_w1, del_b1, del_w2);
    embed_kernel<<<B_*S_, 128>>>(x_enc, tok_w);

    dim3 gQKV(32, 4, 3);
    dim3 gFL(4, 1, 128);
    dim3 gO(32, 4, 1);
    dim3 gFF1(32, 16, 1);

    for (int l = 0; l < L_; l++) {
        // Q/K/V fused (EOUT=2: writes q/k/v fragment buffers)
        fgemm<2,0><<<gQKV, 256, SMGM>>>(
            pxaf, 0, pwqkvf + (long)l*393216, 131072,
            512, 3, pbqkv + l*1536, 512,
            nullptr, 0, 0, 0, nullptr, 0, 0, 0);

        // fused attention: logits + online softmax + PV -> o A-frags
        flash_kernel<<<gFL, 256, SMFL>>>(pqaf, pkbf, pvbf, ptau, pdelta, poaf);

        // O projection -> fp32 tmp
        fgemm<0,0><<<gO, 256, SMGM>>>(
            poaf, 0, pwof + (long)l*131072, 0,
            512, 1, bo + l*D_, 0,
            ptmp, 512, 0, 0, nullptr, 0, 0, 0);
        add_ln_kernel<<<B_*S_, 128>>>(px, ptmp, ln1g + l*D_, ln1b + l*D_, px);

        // FFN
        fgemm<1,1><<<gFF1, 256, SMGM>>>(
            pxaf, 0, pw1f + (long)l*524288, 0,
            512, 1, b1 + l*DFF_, 0,
            nullptr, 0, 0, 0, pfaf, 64, 0, 0);
        fgemm<0,0><<<gO, 256, SMGM>>>(
            pfaf, 0, pw2f + (long)l*524288, 0,
            2048, 1, b2 + l*D_, 0,
            ptmp, 512, 0, 0, nullptr, 0, 0, 0);
        add_ln_kernel<<<B_*S_, 128>>>(px, ptmp, ln2g + l*D_, ln2b + l*D_, px);
    }

    lnf_kernel<<<B_*S_, 128>>>(px, lnfg, lnfb, x_mark, pfin);
    final_kernel<<<B_*NCLS_, 256>>>(pfin, proj_w, proj_b, (float*)d_out);
}

// round 15
// speedup vs baseline: 1.0924x; 1.0924x over previous
#include <cuda_runtime.h>
#include <cuda_fp16.h>
#include <math.h>
#include <stdint.h>

static constexpr int B_ = 16;
static constexpr int S_ = 512;
static constexpr int C_ = 7;
static constexpr int D_ = 512;
static constexpr int H_ = 8;
static constexpr int E_ = 64;
static constexpr int DFF_ = 2048;
static constexpr int L_ = 3;
static constexpr int NCLS_ = 10;
static constexpr int PH_ = 64;

static constexpr long DD   = (long)D_*D_;
static constexpr long BSD  = (long)B_*S_*D_;

// ---------------- fp32 scratch ----------------
__device__ float g_x[BSD];
__device__ float g_tmp[BSD];
__device__ float g_final[BSD];
__device__ float g_tau[B_];
__device__ float g_delta[B_*S_];
__device__ float g_bqkv[L_*3*D_];

// ---------------- fragment-ordered fp16 buffers (u32 = half2 pair over k) ----------------
__device__ uint32_t g_xaf[2097152];     // x A-frags   [mtile64][kc16][2048]
__device__ uint32_t g_qaf[2097152];     // q A-frags   [bh][stile4][kc2][2048]
__device__ uint32_t g_kbf[2097152];     // k B-frags   [bh][ntile4][kc2][2048]
__device__ uint32_t g_vbf[2097152];     // v B-frags   [bh][kc16][1024]
__device__ uint32_t g_oaf[2097152];     // o A-frags   [mtile64][kc16][2048]
__device__ uint32_t g_faf[8388608];     // ffn A-frags [mtile64][kc64][2048]
__device__ uint32_t g_wqkvf[1179648];   // [l*3][ntile4][kc16][2048]
__device__ uint32_t g_wof[393216];      // [l][ntile4][kc16][2048]
__device__ uint32_t g_w1f[1572864];     // [l][ntile16][kc16][2048]
__device__ uint32_t g_w2f[1572864];     // [l][ntile4][kc64][2048]

__device__ __forceinline__ float gelu_f(float x) {
    return 0.5f * x * (1.0f + erff(x * 0.70710678118654752440f));
}
__device__ __forceinline__ void mma16816(float* c, const uint32_t* a, const uint32_t* b) {
    asm volatile(
        "mma.sync.aligned.m16n8k16.row.col.f32.f16.f16.f32 "
        "{%0,%1,%2,%3}, {%4,%5,%6,%7}, {%8,%9}, {%0,%1,%2,%3};"
        : "+f"(c[0]), "+f"(c[1]), "+f"(c[2]), "+f"(c[3])
        : "r"(a[0]), "r"(a[1]), "r"(a[2]), "r"(a[3]), "r"(b[0]), "r"(b[1]));
}
__device__ __forceinline__ uint32_t smem_u32(const void* p) {
    uint32_t a;
    asm("{ .reg .u64 t; cvta.to.shared.u64 t, %1; cvt.u32.u64 %0, t; }" : "=r"(a) : "l"(p));
    return a;
}
__device__ __forceinline__ void cp16(uint32_t dst, const void* src) {
    asm volatile("cp.async.ca.shared.global [%0], [%1], 16;" :: "r"(dst), "l"(src));
}
#define CP_COMMIT() asm volatile("cp.async.commit_group;" ::: "memory")
#define CP_WAIT2()  asm volatile("cp.async.wait_group 2;" ::: "memory")
#define CP_WAIT1()  asm volatile("cp.async.wait_group 1;" ::: "memory")
#define CP_WAIT0()  asm volatile("cp.async.wait_group 0;" ::: "memory")

// fragment index helpers
__device__ __forceinline__ int afrag_off(int m128, int k32) {
    int kt = k32 >> 4, msub = m128 >> 4, r16 = m128 & 15, ck = k32 & 15;
    int reg = (r16 >> 3) + ((ck >> 3) << 1);
    int ln  = ((r16 & 7) << 2) + ((ck >> 1) & 3);
    return kt * 1024 + msub * 128 + ln * 4 + reg;
}
__device__ __forceinline__ int bfrag_off128(int n128, int k32) {
    int kt = k32 >> 4, nsub = n128 >> 3, ck = k32 & 15;
    int ln = ((n128 & 7) << 2) + ((ck & 7) >> 1);
    return kt * 1024 + nsub * 64 + ln * 2 + (ck >> 3);
}

// ========== fragment-plane fp16 GEMM, 128x128 tile, 6-stage paired-chunk pipeline ==========
// EOUT: 0=f32 row-major, 1=A-frag u32 out, 2=qkv frag out (hh selects q/k/v)
// EPI : 0=+bias, 1=+bias+gelu
// 8 warps: mw=wid&3 (32 rows each), nw=wid>>2 (64 cols each)
template<int EOUT, int EPI>
__global__ void __launch_bounds__(256, 2) fgemm(
    const uint32_t* __restrict__ Af, long Az,
    const uint32_t* __restrict__ Bf, long Bz,
    int K, int hmod,
    const float* __restrict__ bias, int biasMul,
    float* __restrict__ C, int ldc, long dC, long mC,
    uint32_t* __restrict__ Of, int NKCH, int mAddMul, int kAddMul)
{
    constexpr int SST = 4096;                 // u32 per stage: A 2048 + B 2048

    extern __shared__ uint32_t smem[];
    const uint32_t sbase = smem_u32(smem);

    const int tid = threadIdx.x, wid = tid >> 5, lane = tid & 31;
    const int mw = wid & 3, nw = wid >> 2;
    const int bz = blockIdx.z;
    const int bb = bz / hmod, hh = bz - bb * hmod;
    const int nchunk = K >> 5;                // 16 or 64 (even, >= 4)

    const uint32_t* Ab = Af + (long)bz * Az + (long)blockIdx.x * nchunk * 2048;
    const uint32_t* Bb = Bf + (long)bz * Bz + (long)blockIdx.y * nchunk * 2048;
    const int m0 = blockIdx.x * 128;
    const int n0 = blockIdx.y * 128;

    float acc[2][8][4];
    #pragma unroll
    for (int i = 0; i < 2; i++)
        #pragma unroll
        for (int j = 0; j < 8; j++)
            #pragma unroll
            for (int r = 0; r < 4; r++) acc[i][j][r] = 0.f;

    auto issue = [&](int c, int st) {
        uint32_t sa = sbase + st * (SST * 4);
        const uint32_t* Ac = Ab + (long)c * 2048;
        cp16(sa + tid * 16, Ac + tid * 4);
        cp16(sa + 4096 + tid * 16, Ac + 1024 + tid * 4);
        uint32_t sb = sa + 8192;
        const uint32_t* Bc = Bb + (long)c * 2048;
        cp16(sb + tid * 16, Bc + tid * 4);
        cp16(sb + 4096 + tid * 16, Bc + 1024 + tid * 4);
    };

    issue(0, 0); CP_COMMIT();
    issue(1, 1); CP_COMMIT();
    issue(2, 2); CP_COMMIT();
    issue(3, 3); CP_COMMIT();

    for (int c = 0; c < nchunk; c += 2) {
        if (c + 4 <= nchunk) { CP_WAIT2(); } else { CP_WAIT0(); }
        __syncthreads();
        if (c + 4 < nchunk) {
            int n4 = c + 4, n5 = c + 5;
            int s4 = n4 % 6, s5 = n5 % 6;
            issue(n4, s4); CP_COMMIT();
            issue(n5, s5); CP_COMMIT();
        }
        #pragma unroll
        for (int cc = 0; cc < 2; cc++) {
            const uint32_t* bAp = smem + ((c + cc) % 6) * SST;
            const uint32_t* bBp = bAp + 2048;
            #pragma unroll
            for (int kt = 0; kt < 2; kt++) {
                uint32_t ah[2][4];
                #pragma unroll
                for (int ms = 0; ms < 2; ms++) {
                    int msub = mw * 2 + ms;
                    *(uint4*)ah[ms] = *(const uint4*)&bAp[((kt * 8 + msub) << 7) + lane * 4];
                }
                #pragma unroll
                for (int ns = 0; ns < 8; ns++) {
                    int nsub = nw * 8 + ns;
                    uint32_t bh[2];
                    *(uint2*)bh = *(const uint2*)&bBp[((kt * 16 + nsub) << 6) + lane * 2];
                    #pragma unroll
                    for (int ms = 0; ms < 2; ms++)
                        mma16816(acc[ms][ns], ah[ms], bh);
                }
            }
        }
    }

    // ---- epilogue ----
    #pragma unroll
    for (int ms = 0; ms < 2; ms++) {
        #pragma unroll
        for (int ns = 0; ns < 8; ns++) {
            int mb = m0 + mw * 32 + ms * 16 + (lane >> 2);
            int n  = n0 + nw * 64 + ns * 8 + (lane & 3) * 2;
            float* cr = acc[ms][ns];
            float b0 = 0.f, b1 = 0.f;
            if (bias) { b0 = bias[hh * biasMul + n]; b1 = bias[hh * biasMul + n + 1]; }
            #pragma unroll
            for (int h = 0; h < 2; h++) {
                int m = mb + h * 8;
                float c0 = cr[h * 2 + 0] + b0, c1 = cr[h * 2 + 1] + b1;
                if (EPI == 1) { c0 = gelu_f(c0); c1 = gelu_f(c1); }
                if (EOUT == 0) {
                    float2 o; o.x = c0; o.y = c1;
                    *(float2*)(C + (long)bb * dC + (long)hh * mC + (long)m * ldc + n) = o;
                } else if (EOUT == 1) {
                    __half2 hv = __floats2half2_rn(c0, c1);
                    long mg = (long)bb * mAddMul + m;
                    int  kg = hh * kAddMul + n;
                    Of[((mg >> 7) * (long)NKCH + (kg >> 5)) * 2048 + afrag_off((int)(mg & 127), kg & 31)] = *(uint32_t*)&hv;
                } else {  // EOUT == 2: QKV
                    int b = m >> 9, sl = m & 511;
                    int hh2 = n >> 6, e = n & 63;
                    if (hh == 0) {
                        __half2 hv = __floats2half2_rn(c0, c1);
                        long base = (((long)(b * 8 + hh2) * 4 + (sl >> 7)) * 2 + (e >> 5)) * 2048;
                        g_qaf[base + afrag_off(sl & 127, e & 31)] = *(uint32_t*)&hv;
                    } else if (hh == 1) {
                        __half2 hv = __floats2half2_rn(c0, c1);
                        long base = (((long)(b * 8 + hh2) * 4 + (sl >> 7)) * 2 + (e >> 5)) * 2048;
                        g_kbf[base + bfrag_off128(sl & 127, e & 31)] = *(uint32_t*)&hv;
                    } else {
                        __half* v16 = (__half*)g_vbf;
                        #pragma unroll
                        for (int q = 0; q < 2; q++) {
                            int ee = e + q;
                            float vv = q ? c1 : c0;
                            long u32i = (((long)(b * 8 + hh2) * 16 + (sl >> 5)) * 1024)
                                      + ((sl >> 4) & 1) * 512 + (ee >> 3) * 64
                                      + (((ee & 7) << 2) + ((sl & 7) >> 1)) * 2 + ((sl & 15) >> 3);
                            v16[u32i * 2 + (sl & 1)] = __float2half_rn(vv);
                        }
                    }
                }
            }
        }
    }
}

// ================= fused flash attention =================
// grid (4, 1, 128): x=q-tile, z=bh.  8 warps x 16 Q-rows, full 128-col K tiles per warp.
__global__ void __launch_bounds__(256, 1) flash_kernel(
    const uint32_t* __restrict__ Qf, const uint32_t* __restrict__ Kf,
    const uint32_t* __restrict__ Vf,
    const float* __restrict__ tau, const float* __restrict__ delta,
    uint32_t* __restrict__ Of)
{
    extern __shared__ uint32_t smem[];
    const uint32_t sbase = smem_u32(smem);
    float* sdelta = (float*)(smem + 16384);

    const int tid = threadIdx.x, wid = tid >> 5, lane = tid & 31;
    const int qt = blockIdx.x;
    const int bh = blockIdx.z;
    const int b = bh >> 3, h = bh & 7;

    const float tv = 0.125f * tau[b];
    #pragma unroll
    for (int i = 0; i < 2; i++)
        sdelta[tid + i*256] = 0.125f * delta[b*512 + tid + i*256];

    // Q a-frags: 4 k16 steps (E=64), resident in regs
    uint32_t qf[4][4];
    {
        const uint32_t* Qb = Qf + ((long)bh*4 + qt) * 4096;
        #pragma unroll
        for (int ks = 0; ks < 4; ks++) {
            int kc = ks >> 1, kt = ks & 1;
            *(uint4*)qf[ks] = *(const uint4*)&Qb[kc*2048 + kt*1024 + wid*128 + lane*4];
        }
    }

    const uint32_t* Kb = Kf + (long)bh * 16384;
    const uint32_t* Vb = Vf + (long)bh * 16384;

    auto issue = [&](int t, int st) {
        uint32_t sK = sbase + st * 32768;
        uint32_t sV = sK + 16384;
        #pragma unroll
        for (int j = 0; j < 4; j++) {
            cp16(sK + (tid*4 + j*1024)*4, Kb + (long)t*4096 + tid*4 + j*1024);
            cp16(sV + (tid*4 + j*1024)*4, Vb + (long)t*4096 + tid*4 + j*1024);
        }
    };

    float oacc[8][4];
    #pragma unroll
    for (int ns = 0; ns < 8; ns++)
        #pragma unroll
        for (int r = 0; r < 4; r++) oacc[ns][r] = 0.f;
    float m_r = -1e30f, m_r8 = -1e30f, l_r = 0.f, l_r8 = 0.f;

    issue(0, 0); CP_COMMIT();

    for (int t = 0; t < 4; t++) {
        if (t + 1 < 4) { issue(t + 1, (t + 1) & 1); CP_COMMIT(); CP_WAIT1(); }
        else { CP_WAIT0(); }
        __syncthreads();
        const uint32_t* sK = smem + (t & 1) * 8192;
        const uint32_t* sV = sK + 4096;

        // S = Q K^T  (M=16/warp, N=128, k=64)
        float sacc[16][4];
        #pragma unroll
        for (int ns = 0; ns < 16; ns++)
            #pragma unroll
            for (int r = 0; r < 4; r++) sacc[ns][r] = 0.f;
        #pragma unroll
        for (int ks = 0; ks < 4; ks++) {
            int kc = ks >> 1, kt = ks & 1;
            #pragma unroll
            for (int ns = 0; ns < 16; ns++) {
                uint32_t bf[2];
                *(uint2*)bf = *(const uint2*)&sK[kc*2048 + kt*1024 + ns*64 + lane*2];
                mma16816(sacc[ns], qf[ks], bf);
            }
        }
        // scale + delta
        #pragma unroll
        for (int ns = 0; ns < 16; ns++) {
            int c = t*128 + ns*8 + (lane & 3)*2;
            float d0 = sdelta[c], d1 = sdelta[c + 1];
            sacc[ns][0] = fmaf(sacc[ns][0], tv, d0);
            sacc[ns][1] = fmaf(sacc[ns][1], tv, d1);
            sacc[ns][2] = fmaf(sacc[ns][2], tv, d0);
            sacc[ns][3] = fmaf(sacc[ns][3], tv, d1);
        }
        // tile row max
        float tm_r = -1e30f, tm_r8 = -1e30f;
        #pragma unroll
        for (int ns = 0; ns < 16; ns++) {
            tm_r  = fmaxf(tm_r,  fmaxf(sacc[ns][0], sacc[ns][1]));
            tm_r8 = fmaxf(tm_r8, fmaxf(sacc[ns][2], sacc[ns][3]));
        }
        #pragma unroll
        for (int o = 1; o <= 2; o <<= 1) {
            tm_r  = fmaxf(tm_r,  __shfl_xor_sync(0xffffffffu, tm_r,  o));
            tm_r8 = fmaxf(tm_r8, __shfl_xor_sync(0xffffffffu, tm_r8, o));
        }
        float mn_r = fmaxf(m_r, tm_r), mn_r8 = fmaxf(m_r8, tm_r8);
        float cor_r = __expf(m_r - mn_r), cor_r8 = __expf(m_r8 - mn_r8);
        m_r = mn_r; m_r8 = mn_r8;
        float rs_r = 0.f, rs_r8 = 0.f;
        #pragma unroll
        for (int ns = 0; ns < 16; ns++) {
            sacc[ns][0] = __expf(sacc[ns][0] - m_r);
            sacc[ns][1] = __expf(sacc[ns][1] - m_r);
            sacc[ns][2] = __expf(sacc[ns][2] - m_r8);
            sacc[ns][3] = __expf(sacc[ns][3] - m_r8);
            rs_r  += sacc[ns][0] + sacc[ns][1];
            rs_r8 += sacc[ns][2] + sacc[ns][3];
        }
        #pragma unroll
        for (int o = 1; o <= 2; o <<= 1) {
            rs_r  += __shfl_xor_sync(0xffffffffu, rs_r,  o);
            rs_r8 += __shfl_xor_sync(0xffffffffu, rs_r8, o);
        }
        l_r = l_r * cor_r + rs_r;
        l_r8 = l_r8 * cor_r8 + rs_r8;
        #pragma unroll
        for (int ns = 0; ns < 8; ns++) {
            oacc[ns][0] *= cor_r;  oacc[ns][1] *= cor_r;
            oacc[ns][2] *= cor_r8; oacc[ns][3] *= cor_r8;
        }
        // O += P V
        #pragma unroll
        for (int kk = 0; kk < 8; kk++) {
            uint32_t pa[4];
            __half2 hv;
            hv = __floats2half2_rn(sacc[2*kk][0],   sacc[2*kk][1]);   pa[0] = *(uint32_t*)&hv;
            hv = __floats2half2_rn(sacc[2*kk][2],   sacc[2*kk][3]);   pa[1] = *(uint32_t*)&hv;
            hv = __floats2half2_rn(sacc[2*kk+1][0], sacc[2*kk+1][1]); pa[2] = *(uint32_t*)&hv;
            hv = __floats2half2_rn(sacc[2*kk+1][2], sacc[2*kk+1][3]); pa[3] = *(uint32_t*)&hv;
            int kc2 = kk >> 1, kt2 = kk & 1;
            #pragma unroll
            for (int ns = 0; ns < 8; ns++) {
                uint32_t bf[2];
                *(uint2*)bf = *(const uint2*)&sV[kc2*1024 + kt2*512 + ns*64 + lane*2];
                mma16816(oacc[ns], pa, bf);
            }
        }
        __syncthreads();
    }

    // normalize + write O a-frags
    float inv_r = 1.f / l_r, inv_r8 = 1.f / l_r8;
    int r16 = lane >> 2;
    #pragma unroll
    for (int ns = 0; ns < 8; ns++) {
        int e = ns*8 + (lane & 3)*2;
        __half2 h0 = __floats2half2_rn(oacc[ns][0]*inv_r,  oacc[ns][1]*inv_r);
        __half2 h1 = __floats2half2_rn(oacc[ns][2]*inv_r8, oacc[ns][3]*inv_r8);
        long base = ((long)(b*4 + qt) * 16 + h*2 + (e >> 5)) * 2048;
        Of[base + afrag_off(wid*16 + r16,     e & 31)] = *(uint32_t*)&h0;
        Of[base + afrag_off(wid*16 + r16 + 8, e & 31)] = *(uint32_t*)&h1;
    }
}

// ---------------- fused weight fragment conversion (+ bias concat) ----------------
__device__ __forceinline__ void cvt_one(const float* __restrict__ W, uint32_t* __restrict__ dst,
                                        long i, int N, int Kd, long perL)
{
    long Kh = Kd >> 1;
    int kp = (int)(i % Kh);
    long r = i / Kh;
    int n = (int)(r % N);
    int l = (int)(r / N);
    const float* src = W + ((long)l * N + n) * Kd + kp * 2;
    float2 v = *(const float2*)src;
    __half2 h = __floats2half2_rn(v.x, v.y);
    int k = kp * 2;
    long base = (long)l * perL + ((long)(n >> 7) * (Kd >> 5) + (k >> 5)) * 2048;
    dst[base + bfrag_off128(n & 127, k & 31)] = *(uint32_t*)&h;
}

static constexpr long NQKV = (long)L_ * 3 * 512 * 256;          // 1179648
static constexpr long NWO  = (long)L_ * 512 * 256;              //  393216
static constexpr long NW1  = (long)L_ * 2048 * 256;             // 1572864
static constexpr long NW2  = (long)L_ * 512 * 1024;             // 1572864
static constexpr long CVT_TOT = NQKV + NWO + NW1 + NW2 + L_*3*D_;

__global__ void cvt_all(const float* __restrict__ Wq, const float* __restrict__ Wk,
                        const float* __restrict__ Wv, const float* __restrict__ Wo,
                        const float* __restrict__ W1, const float* __restrict__ W2,
                        const float* __restrict__ bq, const float* __restrict__ bk,
                        const float* __restrict__ bv,
                        uint32_t* __restrict__ dqkv, uint32_t* __restrict__ dwo,
                        uint32_t* __restrict__ dw1, uint32_t* __restrict__ dw2,
                        float* __restrict__ dbias)
{
    long i = (long)blockIdx.x * 256 + threadIdx.x;
    if (i < NQKV) {
        int kp = (int)(i & 255);
        int n  = (int)((i >> 8) & 511);
        int ls = (int)(i >> 17);
        int l = ls / 3, s = ls - l * 3;
        const float* src = (s == 0 ? Wq : (s == 1 ? Wk : Wv)) + (long)l * DD + (long)n * 512 + kp * 2;
        float2 v = *(const float2*)src;
        __half2 h = __floats2half2_rn(v.x, v.y);
        int k = kp * 2;
        long base = (long)ls * 131072 + ((long)(n >> 7) * 16 + (k >> 5)) * 2048;
        dqkv[base + bfrag_off128(n & 127, k & 31)] = *(uint32_t*)&h;
        return;
    }
    i -= NQKV;
    if (i < NWO) { cvt_one(Wo, dwo, i, 512, 512, 131072); return; }
    i -= NWO;
    if (i < NW1) { cvt_one(W1, dw1, i, 2048, 512, 524288); return; }
    i -= NW1;
    if (i < NW2) { cvt_one(W2, dw2, i, 512, 2048, 524288); return; }
    i -= NW2;
    if (i < L_*3*D_) {
        int l = (int)i / (3*D_);
        int rem = (int)i - l*3*D_;
        int sel = rem / D_;
        int off = rem - sel*D_;
        dbias[i] = (sel == 0 ? bq : (sel == 1 ? bk : bv))[l*D_ + off];
    }
}

// ---------------- tau/delta projectors ----------------
__global__ void proj_kernel(const float* __restrict__ x_enc,
                            const float* __restrict__ tau_conv, const float* __restrict__ tau_w1,
                            const float* __restrict__ tau_b1, const float* __restrict__ tau_w2,
                            const float* __restrict__ del_conv, const float* __restrict__ del_w1,
                            const float* __restrict__ del_b1, const float* __restrict__ del_w2)
{
    int b = blockIdx.x;
    int tid = threadIdx.x;               // 256
    __shared__ float s_mean[C_], s_std[C_], s_yt[C_], s_yd[C_], s_ht[PH_], s_hd[PH_];

    if (tid < C_) {
        float s = 0.f, s2 = 0.f;
        for (int i = 0; i < S_; i++) {
            float v = x_enc[((long)b*S_ + i)*C_ + tid];
            s += v; s2 += v*v;
        }
        float mu = s * (1.f/S_);
        s_mean[tid] = mu;
        s_std[tid] = sqrtf(fmaxf(s2*(1.f/S_) - mu*mu, 0.f) + 1e-5f);
    }
    int w = tid >> 5, lane = tid & 31;
    if (w < C_) {
        int j = w;
        int jm = (j+6)%7, jp = (j+1)%7;
        float at = 0.f, ad = 0.f;
        for (int i = lane; i < S_; i += 32) {
            const float* xr = x_enc + ((long)b*S_ + i)*C_;
            float x0 = xr[jm], x1 = xr[j], x2 = xr[jp];
            const float* wt = tau_conv + i*3;
            const float* wd = del_conv + i*3;
            at += wt[0]*x0 + wt[1]*x1 + wt[2]*x2;
            ad += wd[0]*x0 + wd[1]*x1 + wd[2]*x2;
        }
        #pragma unroll
        for (int o = 16; o; o >>= 1) {
            at += __shfl_xor_sync(0xffffffffu, at, o);
            ad += __shfl_xor_sync(0xffffffffu, ad, o);
        }
        if (lane == 0) { s_yt[j] = at; s_yd[j] = ad; }
    }
    __syncthreads();
    if (tid < PH_) {
        float st = tau_b1[tid], sd = del_b1[tid];
        #pragma unroll
        for (int f = 0; f < 14; f++) {
            float ft = (f < 7) ? s_yt[f] : s_std[f-7];
            float fd = (f < 7) ? s_yd[f] : s_mean[f-7];
            st += tau_w1[tid*14 + f] * ft;
            sd += del_w1[tid*14 + f] * fd;
        }
        s_ht[tid] = fmaxf(st, 0.f);
        s_hd[tid] = fmaxf(sd, 0.f);
    }
    __syncthreads();
    if (tid < 32) {
        float t = s_ht[tid]*tau_w2[tid] + s_ht[tid+32]*tau_w2[tid+32];
        #pragma unroll
        for (int o = 16; o; o >>= 1) t += __shfl_xor_sync(0xffffffffu, t, o);
        if (tid == 0) g_tau[b] = expf(t);
    }
    for (int s = tid; s < S_; s += 256) {
        float acc = 0.f;
        const float* wr = del_w2 + s*PH_;
        #pragma unroll
        for (int p = 0; p < PH_; p++) acc += s_hd[p] * wr[p];
        g_delta[(long)b*S_ + s] = acc;
    }
}

// ---------------- token embedding + PE (fp32 + A-frag out) ----------------
__global__ void embed_kernel(const float* __restrict__ x_enc, const float* __restrict__ tok_w)
{
    int row = blockIdx.x;                // b*S + s
    int b = row >> 9, s = row & 511;
    __shared__ float xs[3][C_];
    int tid = threadIdx.x;               // 128
    if (tid < 21) {
        int r = tid / 7, c = tid % 7;
        int sp = (s - 1 + r + S_) % S_;
        xs[r][c] = x_enc[((long)b*S_ + sp)*C_ + c];
    }
    __syncthreads();
    #pragma unroll
    for (int i = 0; i < 2; i++) {
        int d = 2*tid + i*256;
        float div = expf((float)d * (-9.2103403719761836f / (float)D_));
        float ang = (float)s * div;
        float pe0 = sinf(ang), pe1 = cosf(ang);
        float a0 = pe0, a1 = pe1;
        const float* w0 = tok_w + (long)d*21;
        const float* w1 = w0 + 21;
        #pragma unroll
        for (int r = 0; r < 3; r++)
            #pragma unroll
            for (int c = 0; c < 7; c++) {
                float xv = xs[r][c];
                a0 = fmaf(w0[c*3 + r], xv, a0);
                a1 = fmaf(w1[c*3 + r], xv, a1);
            }
        float2 o; o.x = a0; o.y = a1;
        *(float2*)(g_x + (long)row*D_ + d) = o;
        __half2 hv = __floats2half2_rn(a0, a1);
        g_xaf[((long)(row >> 7) * 16 + (d >> 5)) * 2048 + afrag_off(row & 127, d & 31)] = *(uint32_t*)&hv;
    }
}

// ---------------- residual add + LayerNorm (fp32 + A-frag out) ----------------
__global__ void add_ln_kernel(const float* __restrict__ xr, const float* __restrict__ ar,
                              const float* __restrict__ g, const float* __restrict__ bt,
                              float* __restrict__ out)
{
    long row = blockIdx.x;
    int tid = threadIdx.x;               // 128
    const float* xp = xr + row*D_;
    const float* ap = ar + row*D_;
    float v[4];
    {
        float2 x0 = *(const float2*)(xp + 2*tid);
        float2 a0 = *(const float2*)(ap + 2*tid);
        float2 x1 = *(const float2*)(xp + 2*tid + 256);
        float2 a1 = *(const float2*)(ap + 2*tid + 256);
        v[0] = x0.x + a0.x; v[1] = x0.y + a0.y;
        v[2] = x1.x + a1.x; v[3] = x1.y + a1.y;
    }
    float s = v[0]+v[1]+v[2]+v[3];
    float s2 = v[0]*v[0]+v[1]*v[1]+v[2]*v[2]+v[3]*v[3];
    __shared__ float shs[4], sh2[4];
    #pragma unroll
    for (int o = 16; o; o >>= 1) {
        s  += __shfl_xor_sync(0xffffffffu, s, o);
        s2 += __shfl_xor_sync(0xffffffffu, s2, o);
    }
    int w = tid >> 5, lane = tid & 31;
    if (lane == 0) { shs[w] = s; sh2[w] = s2; }
    __syncthreads();
    s  = shs[0] + shs[1] + shs[2] + shs[3];
    s2 = sh2[0] + sh2[1] + sh2[2] + sh2[3];
    float mean = s * (1.f/D_);
    float var = s2 * (1.f/D_) - mean*mean;
    float r = rsqrtf(var + 1e-5f);
    #pragma unroll
    for (int i = 0; i < 2; i++) {
        int c = 2*tid + i*256;
        float n0 = (v[i*2]   - mean) * r * g[c]   + bt[c];
        float n1 = (v[i*2+1] - mean) * r * g[c+1] + bt[c+1];
        float2 o; o.x = n0; o.y = n1;
        *(float2*)(out + row*D_ + c) = o;
        __half2 hv = __floats2half2_rn(n0, n1);
        g_xaf[((long)(row >> 7) * 16 + (c >> 5)) * 2048 + afrag_off((int)(row & 127), c & 31)] = *(uint32_t*)&hv;
    }
}

// ---------------- final LN + GELU + mask ----------------
__global__ void lnf_kernel(const float* __restrict__ xr,
                           const float* __restrict__ g, const float* __restrict__ bt,
                           const float* __restrict__ mark, float* __restrict__ out)
{
    long row = blockIdx.x;
    int tid = threadIdx.x;               // 128
    const float* xp = xr + row*D_;
    float v[4];
    float s = 0.f, s2 = 0.f;
    #pragma unroll
    for (int i = 0; i < 4; i++) {
        float t = xp[tid + i*128];
        v[i] = t; s += t; s2 += t*t;
    }
    __shared__ float shs[4], sh2[4];
    #pragma unroll
    for (int o = 16; o; o >>= 1) {
        s  += __shfl_xor_sync(0xffffffffu, s, o);
        s2 += __shfl_xor_sync(0xffffffffu, s2, o);
    }
    int w = tid >> 5, lane = tid & 31;
    if (lane == 0) { shs[w] = s; sh2[w] = s2; }
    __syncthreads();
    s  = shs[0] + shs[1] + shs[2] + shs[3];
    s2 = sh2[0] + sh2[1] + sh2[2] + sh2[3];
    float mean = s * (1.f/D_);
    float var = s2 * (1.f/D_) - mean*mean;
    float r = rsqrtf(var + 1e-5f);
    float mk = mark[row];
    #pragma unroll
    for (int i = 0; i < 4; i++) {
        int c = tid + i*128;
        float val = (v[i] - mean) * r * g[c] + bt[c];
        out[row*D_ + c] = gelu_f(val) * mk;
    }
}

// ---------------- final classifier GEMV ----------------
__global__ void final_kernel(const float* __restrict__ gfin, const float* __restrict__ pw,
                             const float* __restrict__ pb, float* __restrict__ out)
{
    int idx = blockIdx.x;
    int b = idx / NCLS_, n = idx - b*NCLS_;
    const float* gp = gfin + (long)b*S_*D_;
    const float* wp = pw + (long)n*S_*D_;
    float s = 0.f;
    for (int k = threadIdx.x*4; k < S_*D_; k += 256*4) {
        float4 a  = *(const float4*)(gp + k);
        float4 w4 = *(const float4*)(wp + k);
        s += a.x*w4.x + a.y*w4.y + a.z*w4.z + a.w*w4.w;
    }
    __shared__ float sh[8];
    #pragma unroll
    for (int o = 16; o; o >>= 1) s += __shfl_xor_sync(0xffffffffu, s, o);
    if ((threadIdx.x & 31) == 0) sh[threadIdx.x >> 5] = s;
    __syncthreads();
    if (threadIdx.x == 0) {
        float t = 0.f;
        #pragma unroll
        for (int i = 0; i < 8; i++) t += sh[i];
        out[idx] = t + pb[n];
    }
}

// ---------------- host ----------------
extern "C" void kernel_launch(void* const* d_in, const int* in_sizes, int n_in,
                              void* d_out, int out_size)
{
    const float* x_enc    = (const float*)d_in[0];
    const float* x_mark   = (const float*)d_in[1];
    const float* tok_w    = (const float*)d_in[2];
    const float* Wq       = (const float*)d_in[3];
    const float* bq       = (const float*)d_in[4];
    const float* Wk       = (const float*)d_in[5];
    const float* bk       = (const float*)d_in[6];
    const float* Wv       = (const float*)d_in[7];
    const float* bv       = (const float*)d_in[8];
    const float* Wo       = (const float*)d_in[9];
    const float* bo       = (const float*)d_in[10];
    const float* W1       = (const float*)d_in[11];
    const float* b1       = (const float*)d_in[12];
    const float* W2       = (const float*)d_in[13];
    const float* b2       = (const float*)d_in[14];
    const float* ln1g     = (const float*)d_in[15];
    const float* ln1b     = (const float*)d_in[16];
    const float* ln2g     = (const float*)d_in[17];
    const float* ln2b     = (const float*)d_in[18];
    const float* lnfg     = (const float*)d_in[19];
    const float* lnfb     = (const float*)d_in[20];
    const float* proj_w   = (const float*)d_in[21];
    const float* proj_b   = (const float*)d_in[22];
    const float* tau_conv = (const float*)d_in[23];
    const float* tau_w1   = (const float*)d_in[24];
    const float* tau_b1   = (const float*)d_in[25];
    const float* tau_w2   = (const float*)d_in[26];
    const float* del_conv = (const float*)d_in[27];
    const float* del_w1   = (const float*)d_in[28];
    const float* del_b1   = (const float*)d_in[29];
    const float* del_w2   = (const float*)d_in[30];

    float *px, *ptmp, *ptau, *pdelta, *pfin, *pbqkv;
    uint32_t *pxaf, *pqaf, *pkbf, *pvbf, *poaf, *pfaf, *pwqkvf, *pwof, *pw1f, *pw2f;
    cudaGetSymbolAddress((void**)&px,    g_x);
    cudaGetSymbolAddress((void**)&ptmp,  g_tmp);
    cudaGetSymbolAddress((void**)&ptau,  g_tau);
    cudaGetSymbolAddress((void**)&pdelta,g_delta);
    cudaGetSymbolAddress((void**)&pfin,  g_final);
    cudaGetSymbolAddress((void**)&pbqkv, g_bqkv);
    cudaGetSymbolAddress((void**)&pxaf,  g_xaf);
    cudaGetSymbolAddress((void**)&pqaf,  g_qaf);
    cudaGetSymbolAddress((void**)&pkbf,  g_kbf);
    cudaGetSymbolAddress((void**)&pvbf,  g_vbf);
    cudaGetSymbolAddress((void**)&poaf,  g_oaf);
    cudaGetSymbolAddress((void**)&pfaf,  g_faf);
    cudaGetSymbolAddress((void**)&pwqkvf,g_wqkvf);
    cudaGetSymbolAddress((void**)&pwof,  g_wof);
    cudaGetSymbolAddress((void**)&pw1f,  g_w1f);
    cudaGetSymbolAddress((void**)&pw2f,  g_w2f);

    const int SMGM = 6 * 4096 * 4;             // 98304 (6 stages x 16KB)
    const int SMFL = 2 * 32768 + 2048;         // 67584
    cudaFuncSetAttribute(fgemm<2,0>, cudaFuncAttributeMaxDynamicSharedMemorySize, SMGM);
    cudaFuncSetAttribute(fgemm<0,0>, cudaFuncAttributeMaxDynamicSharedMemorySize, SMGM);
    cudaFuncSetAttribute(fgemm<1,1>, cudaFuncAttributeMaxDynamicSharedMemorySize, SMGM);
    cudaFuncSetAttribute(flash_kernel, cudaFuncAttributeMaxDynamicSharedMemorySize, SMFL);

    // fused weight fragment conversions + bias concat
    cvt_all<<<(int)((CVT_TOT + 255) / 256), 256>>>(
        Wq, Wk, Wv, Wo, W1, W2, bq, bk, bv,
        pwqkvf, pwof, pw1f, pw2f, pbqkv);

    proj_kernel<<<B_, 256>>>(x_enc, tau_conv, tau_w1, tau_b1, tau_w2,
                             del_conv, del_w1, del_b1, del_w2);
    embed_kernel<<<B_*S_, 128>>>(x_enc, tok_w);

    dim3 gQKV(64, 4, 3);
    dim3 gFL(4, 1, 128);
    dim3 gO(64, 4, 1);
    dim3 gFF1(64, 16, 1);

    for (int l = 0; l < L_; l++) {
        // Q/K/V fused (EOUT=2: writes q/k/v fragment buffers)
        fgemm<2,0><<<gQKV, 256, SMGM>>>(
            pxaf, 0, pwqkvf + (long)l*393216, 131072,
            512, 3, pbqkv + l*1536, 512,
            nullptr, 0, 0, 0, nullptr, 0, 0, 0);

        // fused attention: logits + online softmax + PV -> o A-frags
        flash_kernel<<<gFL, 256, SMFL>>>(pqaf, pkbf, pvbf, ptau, pdelta, poaf);

        // O projection -> fp32 tmp
        fgemm<0,0><<<gO, 256, SMGM>>>(
            poaf, 0, pwof + (long)l*131072, 0,
            512, 1, bo + l*D_, 0,
            ptmp, 512, 0, 0, nullptr, 0, 0, 0);
        add_ln_kernel<<<B_*S_, 128>>>(px, ptmp, ln1g + l*D_, ln1b + l*D_, px);

        // FFN
        fgemm<1,1><<<gFF1, 256, SMGM>>>(
            pxaf, 0, pw1f + (long)l*524288, 0,
            512, 1, b1 + l*DFF_, 0,
            nullptr, 0, 0, 0, pfaf, 64, 0, 0);
        fgemm<0,0><<<gO, 256, SMGM>>>(
            pfaf, 0, pw2f + (long)l*524288, 0,
            2048, 1, b2 + l*D_, 0,
            ptmp, 512, 0, 0, nullptr, 0, 0, 0);
        add_ln_kernel<<<B_*S_, 128>>>(px, ptmp, ln2g + l*D_, ln2b + l*D_, px);
    }

    lnf_kernel<<<B_*S_, 128>>>(px, lnfg, lnfb, x_mark, pfin);
    final_kernel<<<B_*NCLS_, 256>>>(pfin, proj_w, proj_b, (float*)d_out);
}